// round 2
// baseline (speedup 1.0000x reference)
#include <cuda_runtime.h>

#define NN 100000
#define NE 1600000
#define D  48
#define DV 12              // float4 chunks per feature row
#define HOPS 10

// ---- scratch (static device globals; no runtime allocation allowed) ----
__device__ float  g_deg[NN];
__device__ float  g_norm[NN];
__device__ float4 g_hn[NN * DV];    // h * norm (gather source)
__device__ float4 g_agg[NN * DV];   // scatter-add accumulator

// ---------------------------------------------------------------------
__global__ void k_zero_deg() {
    int i = blockIdx.x * blockDim.x + threadIdx.x;
    if (i < NN) g_deg[i] = 0.0f;
}

__global__ void k_count_deg(const int* __restrict__ dst) {
    int e = blockIdx.x * blockDim.x + threadIdx.x;
    if (e < NE) atomicAdd(&g_deg[dst[e]], 1.0f);
}

__global__ void k_norm() {
    int i = blockIdx.x * blockDim.x + threadIdx.x;
    if (i < NN) g_norm[i] = rsqrtf(fmaxf(g_deg[i], 1.0f));
}

// hn = features * norm ; agg = 0
__global__ void k_init(const float4* __restrict__ feat) {
    int i = blockIdx.x * blockDim.x + threadIdx.x;
    if (i >= NN * DV) return;
    int node = i / DV;
    float n = g_norm[node];
    float4 f = feat[i];
    g_hn[i]  = make_float4(f.x * n, f.y * n, f.z * n, f.w * n);
    g_agg[i] = make_float4(0.f, 0.f, 0.f, 0.f);
}

// vector f32 reduction to L2 (sm_90+): one 16B message instead of 4 atomics
__device__ __forceinline__ void red4(float4* a, float4 v) {
    asm volatile("red.global.add.v4.f32 [%0], {%1, %2, %3, %4};"
                 :: "l"(a), "f"(v.x), "f"(v.y), "f"(v.z), "f"(v.w)
                 : "memory");
}

// one thread per edge: gather full 192B row (12 independent loads -> MLP),
// then 12 vector reds to the destination row
__global__ void k_edge(const int* __restrict__ src, const int* __restrict__ dst) {
    int e = blockIdx.x * blockDim.x + threadIdx.x;
    if (e >= NE) return;
    int s = src[e];
    int d = dst[e];
    const float4* __restrict__ hp = g_hn + (size_t)s * DV;
    float4* ap = g_agg + (size_t)d * DV;
    float4 v[DV];
#pragma unroll
    for (int c = 0; c < DV; c++) v[c] = __ldg(hp + c);
#pragma unroll
    for (int c = 0; c < DV; c++) red4(ap + c, v[c]);
}

// val = 0.9*agg*norm + 0.1*h0 ;  next hop: hn = val*norm, agg = 0
// last hop: write val (the propagated representation r) to output
template <int LAST>
__global__ void k_combine(const float4* __restrict__ feat, float4* __restrict__ out_r) {
    int i = blockIdx.x * blockDim.x + threadIdx.x;
    if (i >= NN * DV) return;
    int node = i / DV;
    float n = g_norm[node];
    float4 a = g_agg[i];
    float4 f = feat[i];
    float4 val;
    val.x = 0.9f * a.x * n + 0.1f * f.x;
    val.y = 0.9f * a.y * n + 0.1f * f.y;
    val.z = 0.9f * a.z * n + 0.1f * f.z;
    val.w = 0.9f * a.w * n + 0.1f * f.w;
    if (LAST) {
        out_r[i] = val;
    } else {
        g_hn[i]  = make_float4(val.x * n, val.y * n, val.z * n, val.w * n);
        g_agg[i] = make_float4(0.f, 0.f, 0.f, 0.f);
    }
}

// positionwise FFN: rst = relu(h@w1+b1)@w2 + b2 + features
// one thread per node row; weights staged in shared (broadcast reads)
__global__ void k_ffn(const float* __restrict__ h,
                      const float* __restrict__ feat,
                      const float* __restrict__ w1, const float* __restrict__ b1,
                      const float* __restrict__ w2, const float* __restrict__ b2,
                      float* __restrict__ out) {
    __shared__ float s_w1[D * D];
    __shared__ float s_w2[D * D];
    __shared__ float s_b1[D];
    __shared__ float s_b2[D];
    for (int i = threadIdx.x; i < D * D; i += blockDim.x) {
        s_w1[i] = w1[i];
        s_w2[i] = w2[i];
    }
    if (threadIdx.x < D) {
        s_b1[threadIdx.x] = b1[threadIdx.x];
        s_b2[threadIdx.x] = b2[threadIdx.x];
    }
    __syncthreads();

    int node = blockIdx.x * blockDim.x + threadIdx.x;
    if (node >= NN) return;

    float hr[D];
    const float4* hrow = (const float4*)(h + (size_t)node * D);
#pragma unroll
    for (int c = 0; c < DV; c++) {
        float4 v = hrow[c];
        hr[c * 4 + 0] = v.x; hr[c * 4 + 1] = v.y;
        hr[c * 4 + 2] = v.z; hr[c * 4 + 3] = v.w;
    }

    float mid[D];
    for (int j = 0; j < D; j++) {
        float acc = s_b1[j];
#pragma unroll
        for (int k = 0; k < D; k++) acc += hr[k] * s_w1[k * D + j];
        mid[j] = fmaxf(acc, 0.0f);
    }

    const float4* frow = (const float4*)(feat + (size_t)node * D);
    float4* orow = (float4*)(out + (size_t)node * D);
    for (int c = 0; c < DV; c++) {
        float4 f = frow[c];
        float o[4];
#pragma unroll
        for (int q = 0; q < 4; q++) {
            int j = c * 4 + q;
            float acc = s_b2[j];
#pragma unroll
            for (int k = 0; k < D; k++) acc += mid[k] * s_w2[k * D + j];
            o[q] = acc;
        }
        orow[c] = make_float4(o[0] + f.x, o[1] + f.y, o[2] + f.z, o[3] + f.w);
    }
}

// ---------------------------------------------------------------------
extern "C" void kernel_launch(void* const* d_in, const int* in_sizes, int n_in,
                              void* d_out, int out_size) {
    const float* feat = (const float*)d_in[0];
    const int*   src  = (const int*)d_in[1];
    const int*   dst  = (const int*)d_in[2];
    const float* w1   = (const float*)d_in[3];
    const float* b1   = (const float*)d_in[4];
    const float* w2   = (const float*)d_in[5];
    const float* b2   = (const float*)d_in[6];
    float* out = (float*)d_out;

    float*  out_rst = out;                    // first output: rst [NN, D]
    float*  out_r   = out + (size_t)NN * D;   // second output: r  [NN, D]

    const int T = 256;
    int gN   = (NN + T - 1) / T;
    int gE   = (NE + T - 1) / T;
    int gND  = (NN * DV + T - 1) / T;

    k_zero_deg<<<gN, T>>>();
    k_count_deg<<<gE, T>>>(dst);
    k_norm<<<gN, T>>>();
    k_init<<<gND, T>>>((const float4*)feat);

    for (int hop = 0; hop < HOPS; hop++) {
        k_edge<<<gE, T>>>(src, dst);
        if (hop < HOPS - 1)
            k_combine<0><<<gND, T>>>((const float4*)feat, (float4*)out_r);
        else
            k_combine<1><<<gND, T>>>((const float4*)feat, (float4*)out_r);
    }

    const int TF = 128;
    k_ffn<<<(NN + TF - 1) / TF, TF>>>(out_r, feat, w1, b1, w2, b2, out_rst);
}

// round 3
// speedup vs baseline: 3.2802x; 3.2802x over previous
#include <cuda_runtime.h>

#define NN 100000
#define NE 1600000
#define D  48
#define D2 24              // float2 chunks per feature row
#define HOPS 10
#define SCAN_BLKS ((NN + 1023) / 1024)   // 98

// ---- scratch (static device globals; no runtime allocation allowed) ----
__device__ int    g_degi[NN];
__device__ float  g_norm[NN];
__device__ int    g_offs[NN + 1];
__device__ int    g_bsum[128];
__device__ int    g_cursor[NN];
__device__ int    g_csrc[NE];          // CSR: src indices grouped by dst
__device__ float2 g_hnA[NN * D2];      // h*norm ping
__device__ float2 g_hnB[NN * D2];      // h*norm pong

// ---------------------------------------------------------------------
__global__ void k_zero_deg() {
    int i = blockIdx.x * blockDim.x + threadIdx.x;
    if (i < NN) g_degi[i] = 0;
}

__global__ void k_hist(const int* __restrict__ dst) {
    int e = blockIdx.x * blockDim.x + threadIdx.x;
    if (e < NE) atomicAdd(&g_degi[dst[e]], 1);
}

// inclusive scan of g_degi within 1024-blocks; g_offs[i+1] = partial inclusive
__global__ void k_scan1() {
    __shared__ int sh[1024];
    int tid = threadIdx.x;
    int i = blockIdx.x * 1024 + tid;
    sh[tid] = (i < NN) ? g_degi[i] : 0;
    __syncthreads();
#pragma unroll
    for (int off = 1; off < 1024; off <<= 1) {
        int t = (tid >= off) ? sh[tid - off] : 0;
        __syncthreads();
        sh[tid] += t;
        __syncthreads();
    }
    if (i < NN) g_offs[i + 1] = sh[tid];
    if (tid == 1023) g_bsum[blockIdx.x] = sh[1023];
}

__global__ void k_scan2(int nb) {
    if (threadIdx.x == 0 && blockIdx.x == 0) {
        int run = 0;
        for (int b = 0; b < nb; b++) { int t = g_bsum[b]; g_bsum[b] = run; run += t; }
    }
}

__global__ void k_scan3() {
    int i = blockIdx.x * blockDim.x + threadIdx.x;
    if (i > NN) return;
    if (i == 0) { g_offs[0] = 0; return; }
    g_offs[i] += g_bsum[(i - 1) >> 10];
}

// norm from degree; cursor = offs (scatter write positions)
__global__ void k_norm_cursor() {
    int i = blockIdx.x * blockDim.x + threadIdx.x;
    if (i >= NN) return;
    g_norm[i] = rsqrtf(fmaxf((float)g_degi[i], 1.0f));
    g_cursor[i] = g_offs[i];
}

__global__ void k_scatter(const int* __restrict__ src, const int* __restrict__ dst) {
    int e = blockIdx.x * blockDim.x + threadIdx.x;
    if (e >= NE) return;
    int pos = atomicAdd(&g_cursor[dst[e]], 1);
    g_csrc[pos] = src[e];
}

// hnA = features * norm
__global__ void k_init(const float2* __restrict__ feat) {
    int i = blockIdx.x * blockDim.x + threadIdx.x;
    if (i >= NN * D2) return;
    float n = g_norm[i / D2];
    float2 f = feat[i];
    g_hnA[i] = make_float2(f.x * n, f.y * n);
}

// One warp per destination node; lanes 0..23 own one float2 each of the row.
// Gathers src rows from the read buffer, accumulates in registers,
// fuses the APPNP combine + renorm into the epilogue. RB: 0 = read A write B.
template <int LAST, int RB>
__global__ void __launch_bounds__(256) k_prop(const float2* __restrict__ feat,
                                              float2* __restrict__ out_r) {
    int gw = (blockIdx.x * blockDim.x + threadIdx.x) >> 5;
    if (gw >= NN) return;
    int lane = threadIdx.x & 31;
    bool act = lane < D2;
    int idx = act ? lane : 0;

    const float2* __restrict__ hn = RB ? g_hnB : g_hnA;
    int beg = g_offs[gw];
    int end = g_offs[gw + 1];

    float sx = 0.f, sy = 0.f;
    int e = beg;
    for (; e + 3 < end; e += 4) {
        int s0 = __ldg(&g_csrc[e + 0]);
        int s1 = __ldg(&g_csrc[e + 1]);
        int s2 = __ldg(&g_csrc[e + 2]);
        int s3 = __ldg(&g_csrc[e + 3]);
        float2 v0 = __ldg(&hn[(size_t)s0 * D2 + idx]);
        float2 v1 = __ldg(&hn[(size_t)s1 * D2 + idx]);
        float2 v2 = __ldg(&hn[(size_t)s2 * D2 + idx]);
        float2 v3 = __ldg(&hn[(size_t)s3 * D2 + idx]);
        sx += v0.x + v1.x + v2.x + v3.x;
        sy += v0.y + v1.y + v2.y + v3.y;
    }
    for (; e < end; e++) {
        int s = __ldg(&g_csrc[e]);
        float2 v = __ldg(&hn[(size_t)s * D2 + idx]);
        sx += v.x; sy += v.y;
    }

    if (!act) return;
    float nrm = g_norm[gw];
    float2 f = feat[(size_t)gw * D2 + lane];
    float vx = 0.9f * sx * nrm + 0.1f * f.x;
    float vy = 0.9f * sy * nrm + 0.1f * f.y;
    if (LAST) {
        out_r[(size_t)gw * D2 + lane] = make_float2(vx, vy);
    } else {
        float2* __restrict__ o = RB ? g_hnA : g_hnB;
        o[(size_t)gw * D2 + lane] = make_float2(vx * nrm, vy * nrm);
    }
}

// positionwise FFN: rst = relu(h@w1+b1)@w2 + b2 + features
__global__ void k_ffn(const float* __restrict__ h,
                      const float* __restrict__ feat,
                      const float* __restrict__ w1, const float* __restrict__ b1,
                      const float* __restrict__ w2, const float* __restrict__ b2,
                      float* __restrict__ out) {
    __shared__ float s_w1[D * D];
    __shared__ float s_w2[D * D];
    __shared__ float s_b1[D];
    __shared__ float s_b2[D];
    for (int i = threadIdx.x; i < D * D; i += blockDim.x) {
        s_w1[i] = w1[i];
        s_w2[i] = w2[i];
    }
    if (threadIdx.x < D) {
        s_b1[threadIdx.x] = b1[threadIdx.x];
        s_b2[threadIdx.x] = b2[threadIdx.x];
    }
    __syncthreads();

    int node = blockIdx.x * blockDim.x + threadIdx.x;
    if (node >= NN) return;

    float hr[D];
    const float4* hrow = (const float4*)(h + (size_t)node * D);
#pragma unroll
    for (int c = 0; c < D / 4; c++) {
        float4 v = hrow[c];
        hr[c * 4 + 0] = v.x; hr[c * 4 + 1] = v.y;
        hr[c * 4 + 2] = v.z; hr[c * 4 + 3] = v.w;
    }

    float mid[D];
    for (int j = 0; j < D; j++) {
        float acc = s_b1[j];
#pragma unroll
        for (int k = 0; k < D; k++) acc += hr[k] * s_w1[k * D + j];
        mid[j] = fmaxf(acc, 0.0f);
    }

    const float4* frow = (const float4*)(feat + (size_t)node * D);
    float4* orow = (float4*)(out + (size_t)node * D);
    for (int c = 0; c < D / 4; c++) {
        float4 f = frow[c];
        float o[4];
#pragma unroll
        for (int q = 0; q < 4; q++) {
            int j = c * 4 + q;
            float acc = s_b2[j];
#pragma unroll
            for (int k = 0; k < D; k++) acc += mid[k] * s_w2[k * D + j];
            o[q] = acc;
        }
        orow[c] = make_float4(o[0] + f.x, o[1] + f.y, o[2] + f.z, o[3] + f.w);
    }
}

// ---------------------------------------------------------------------
extern "C" void kernel_launch(void* const* d_in, const int* in_sizes, int n_in,
                              void* d_out, int out_size) {
    const float* feat = (const float*)d_in[0];
    const int*   src  = (const int*)d_in[1];
    const int*   dst  = (const int*)d_in[2];
    const float* w1   = (const float*)d_in[3];
    const float* b1   = (const float*)d_in[4];
    const float* w2   = (const float*)d_in[5];
    const float* b2   = (const float*)d_in[6];
    float* out = (float*)d_out;

    float* out_rst = out;                    // first output: rst [NN, D]
    float* out_r   = out + (size_t)NN * D;   // second output: r  [NN, D]

    const int T = 256;
    int gN  = (NN + T - 1) / T;
    int gE  = (NE + T - 1) / T;
    int gND = (NN * D2 + T - 1) / T;
    int gW  = (NN * 32 + T - 1) / T;         // warp-per-node grid

    // ---- CSR build ----
    k_zero_deg<<<gN, T>>>();
    k_hist<<<gE, T>>>(dst);
    k_scan1<<<SCAN_BLKS, 1024>>>();
    k_scan2<<<1, 32>>>(SCAN_BLKS);
    k_scan3<<<(NN + 1 + T - 1) / T, T>>>();
    k_norm_cursor<<<gN, T>>>();
    k_scatter<<<gE, T>>>(src, dst);

    // ---- propagation ----
    k_init<<<gND, T>>>((const float2*)feat);
    for (int hop = 0; hop < HOPS; hop++) {
        int rb = hop & 1;
        if (hop == HOPS - 1) {
            if (rb) k_prop<1, 1><<<gW, T>>>((const float2*)feat, (float2*)out_r);
            else    k_prop<1, 0><<<gW, T>>>((const float2*)feat, (float2*)out_r);
        } else {
            if (rb) k_prop<0, 1><<<gW, T>>>((const float2*)feat, (float2*)out_r);
            else    k_prop<0, 0><<<gW, T>>>((const float2*)feat, (float2*)out_r);
        }
    }

    // ---- FFN + residual ----
    const int TF = 128;
    k_ffn<<<(NN + TF - 1) / TF, TF>>>(out_r, feat, w1, b1, w2, b2, out_rst);
}

// round 4
// speedup vs baseline: 3.8359x; 1.1694x over previous
#include <cuda_runtime.h>
#include <cuda_fp16.h>

#define NN 100000
#define NE 1600000
#define NE_PAD (NE + 3 * NN)      // padded CSR capacity (segments rounded to 4)
#define D  48
#define D2 24                     // half2 / float2 chunks per feature row
#define HOPS 10
#define SCAN_BLKS ((NN + 1023) / 1024)   // 98

// ---- scratch (static device globals; no runtime allocation allowed) ----
__device__ int     g_degi[NN];
__device__ float   g_norm[NN];
__device__ int     g_offs[NN + 1];
__device__ int     g_bsum[128];
__device__ int     g_cursor[NN];
__device__ __align__(16) int g_csrc[NE_PAD];   // CSR src indices grouped by dst (padded w/ NN)
__device__ __half2 g_hnA[(NN + 1) * D2];       // h*norm ping (row NN = zero dummy)
__device__ __half2 g_hnB[(NN + 1) * D2];       // h*norm pong

// ---------------------------------------------------------------------
__global__ void k_zero_deg() {
    int i = blockIdx.x * blockDim.x + threadIdx.x;
    if (i < NN) g_degi[i] = 0;
}

__global__ void k_prefill() {
    int i = blockIdx.x * blockDim.x + threadIdx.x;
    if (i < NE_PAD) g_csrc[i] = NN;   // dummy src -> zero row
}

__global__ void k_hist(const int* __restrict__ dst) {
    int e = blockIdx.x * blockDim.x + threadIdx.x;
    if (e < NE) atomicAdd(&g_degi[dst[e]], 1);
}

// inclusive scan of PADDED degrees within 1024-blocks
__global__ void k_scan1() {
    __shared__ int sh[1024];
    int tid = threadIdx.x;
    int i = blockIdx.x * 1024 + tid;
    sh[tid] = (i < NN) ? ((g_degi[i] + 3) & ~3) : 0;
    __syncthreads();
#pragma unroll
    for (int off = 1; off < 1024; off <<= 1) {
        int t = (tid >= off) ? sh[tid - off] : 0;
        __syncthreads();
        sh[tid] += t;
        __syncthreads();
    }
    if (i < NN) g_offs[i + 1] = sh[tid];
    if (tid == 1023) g_bsum[blockIdx.x] = sh[1023];
}

// exclusive scan of the 98 block sums (single block, parallel)
__global__ void k_scan2() {
    __shared__ int sh[128];
    int t = threadIdx.x;
    int v = (t < SCAN_BLKS) ? g_bsum[t] : 0;
    sh[t] = v;
    __syncthreads();
#pragma unroll
    for (int off = 1; off < 128; off <<= 1) {
        int u = (t >= off) ? sh[t - off] : 0;
        __syncthreads();
        sh[t] += u;
        __syncthreads();
    }
    if (t < SCAN_BLKS) g_bsum[t] = sh[t] - v;
}

// finalize offs; fused norm + cursor
__global__ void k_scan3() {
    int i = blockIdx.x * blockDim.x + threadIdx.x;
    if (i > NN) return;
    int o;
    if (i == 0) { g_offs[0] = 0; o = 0; }
    else        { o = g_offs[i] + g_bsum[(i - 1) >> 10]; g_offs[i] = o; }
    if (i < NN) {
        g_cursor[i] = o;
        g_norm[i] = rsqrtf(fmaxf((float)g_degi[i], 1.0f));
    }
}

__global__ void k_scatter(const int* __restrict__ src, const int* __restrict__ dst) {
    int e = blockIdx.x * blockDim.x + threadIdx.x;
    if (e >= NE) return;
    int pos = atomicAdd(&g_cursor[dst[e]], 1);
    g_csrc[pos] = src[e];
}

// hnA = half2(features * norm); zero dummy row NN in both buffers
__global__ void k_init(const float2* __restrict__ feat) {
    int i = blockIdx.x * blockDim.x + threadIdx.x;
    if (i >= (NN + 1) * D2) return;
    int node = i / D2;
    if (node == NN) {
        g_hnA[i] = __floats2half2_rn(0.f, 0.f);
        g_hnB[i] = __floats2half2_rn(0.f, 0.f);
        return;
    }
    float n = g_norm[node];
    float2 f = feat[i];
    g_hnA[i] = __floats2half2_rn(f.x * n, f.y * n);
}

// One warp per destination node; lanes 0..23 own one half2 each (96B row
// = single 128B line). Segment length is a multiple of 4 -> aligned int4
// index loads, no tail. Accumulate fp32; fused APPNP combine + renorm.
template <int LAST, int RB>
__global__ void __launch_bounds__(256) k_prop(const float2* __restrict__ feat,
                                              float2* __restrict__ out_r) {
    int gw = (blockIdx.x * blockDim.x + threadIdx.x) >> 5;
    if (gw >= NN) return;
    int lane = threadIdx.x & 31;
    bool act = lane < D2;
    int idx = act ? lane : 0;

    const __half2* __restrict__ hn = RB ? g_hnB : g_hnA;
    int beg = g_offs[gw];
    int end = g_offs[gw + 1];

    float sx = 0.f, sy = 0.f;
    for (int e = beg; e < end; e += 4) {
        int4 ss = __ldg((const int4*)&g_csrc[e]);
        __half2 v0 = __ldg(&hn[(size_t)ss.x * D2 + idx]);
        __half2 v1 = __ldg(&hn[(size_t)ss.y * D2 + idx]);
        __half2 v2 = __ldg(&hn[(size_t)ss.z * D2 + idx]);
        __half2 v3 = __ldg(&hn[(size_t)ss.w * D2 + idx]);
        float2 f0 = __half22float2(v0);
        float2 f1 = __half22float2(v1);
        float2 f2 = __half22float2(v2);
        float2 f3 = __half22float2(v3);
        sx += (f0.x + f1.x) + (f2.x + f3.x);
        sy += (f0.y + f1.y) + (f2.y + f3.y);
    }

    if (!act) return;
    float nrm = g_norm[gw];
    float2 f = feat[(size_t)gw * D2 + lane];
    float vx = 0.9f * sx * nrm + 0.1f * f.x;
    float vy = 0.9f * sy * nrm + 0.1f * f.y;
    if (LAST) {
        out_r[(size_t)gw * D2 + lane] = make_float2(vx, vy);
    } else {
        __half2* __restrict__ o = RB ? g_hnA : g_hnB;
        o[(size_t)gw * D2 + lane] = __floats2half2_rn(vx * nrm, vy * nrm);
    }
}

// positionwise FFN: rst = relu(h@w1+b1)@w2 + b2 + features
// one thread per node row; weights in shared, float4-vectorized inner loops
__global__ void k_ffn(const float* __restrict__ h,
                      const float* __restrict__ feat,
                      const float* __restrict__ w1, const float* __restrict__ b1,
                      const float* __restrict__ w2, const float* __restrict__ b2,
                      float* __restrict__ out) {
    __shared__ float s_w1[D * D];
    __shared__ float s_w2[D * D];
    __shared__ float s_b1[D];
    __shared__ float s_b2[D];
    for (int i = threadIdx.x; i < D * D; i += blockDim.x) {
        s_w1[i] = w1[i];
        s_w2[i] = w2[i];
    }
    if (threadIdx.x < D) {
        s_b1[threadIdx.x] = b1[threadIdx.x];
        s_b2[threadIdx.x] = b2[threadIdx.x];
    }
    __syncthreads();

    int node = blockIdx.x * blockDim.x + threadIdx.x;
    if (node >= NN) return;

    float hr[D];
    const float4* hrow = (const float4*)(h + (size_t)node * D);
#pragma unroll
    for (int c = 0; c < D / 4; c++) {
        float4 v = hrow[c];
        hr[c * 4 + 0] = v.x; hr[c * 4 + 1] = v.y;
        hr[c * 4 + 2] = v.z; hr[c * 4 + 3] = v.w;
    }

    float mid[D];
#pragma unroll
    for (int jc = 0; jc < D / 4; jc++) {
        float4 acc = *(const float4*)&s_b1[jc * 4];
#pragma unroll
        for (int k = 0; k < D; k++) {
            float4 w = *(const float4*)&s_w1[k * D + jc * 4];
            float hk = hr[k];
            acc.x += hk * w.x; acc.y += hk * w.y;
            acc.z += hk * w.z; acc.w += hk * w.w;
        }
        mid[jc * 4 + 0] = fmaxf(acc.x, 0.f);
        mid[jc * 4 + 1] = fmaxf(acc.y, 0.f);
        mid[jc * 4 + 2] = fmaxf(acc.z, 0.f);
        mid[jc * 4 + 3] = fmaxf(acc.w, 0.f);
    }

    const float4* frow = (const float4*)(feat + (size_t)node * D);
    float4* orow = (float4*)(out + (size_t)node * D);
#pragma unroll
    for (int jc = 0; jc < D / 4; jc++) {
        float4 acc = *(const float4*)&s_b2[jc * 4];
#pragma unroll
        for (int k = 0; k < D; k++) {
            float4 w = *(const float4*)&s_w2[k * D + jc * 4];
            float mk = mid[k];
            acc.x += mk * w.x; acc.y += mk * w.y;
            acc.z += mk * w.z; acc.w += mk * w.w;
        }
        float4 f = frow[jc];
        orow[jc] = make_float4(acc.x + f.x, acc.y + f.y, acc.z + f.z, acc.w + f.w);
    }
}

// ---------------------------------------------------------------------
extern "C" void kernel_launch(void* const* d_in, const int* in_sizes, int n_in,
                              void* d_out, int out_size) {
    const float* feat = (const float*)d_in[0];
    const int*   src  = (const int*)d_in[1];
    const int*   dst  = (const int*)d_in[2];
    const float* w1   = (const float*)d_in[3];
    const float* b1   = (const float*)d_in[4];
    const float* w2   = (const float*)d_in[5];
    const float* b2   = (const float*)d_in[6];
    float* out = (float*)d_out;

    float* out_rst = out;                    // first output: rst [NN, D]
    float* out_r   = out + (size_t)NN * D;   // second output: r  [NN, D]

    const int T = 256;
    int gN  = (NN + T - 1) / T;
    int gE  = (NE + T - 1) / T;
    int gP  = (NE_PAD + T - 1) / T;
    int gI  = ((NN + 1) * D2 + T - 1) / T;
    int gW  = (NN * 32 + T - 1) / T;         // warp-per-node grid

    // ---- CSR build (padded segments) ----
    k_zero_deg<<<gN, T>>>();
    k_prefill<<<gP, T>>>();
    k_hist<<<gE, T>>>(dst);
    k_scan1<<<SCAN_BLKS, 1024>>>();
    k_scan2<<<1, 128>>>();
    k_scan3<<<(NN + 1 + T - 1) / T, T>>>();
    k_scatter<<<gE, T>>>(src, dst);

    // ---- propagation ----
    k_init<<<gI, T>>>((const float2*)feat);
    for (int hop = 0; hop < HOPS; hop++) {
        int rb = hop & 1;
        if (hop == HOPS - 1) {
            if (rb) k_prop<1, 1><<<gW, T>>>((const float2*)feat, (float2*)out_r);
            else    k_prop<1, 0><<<gW, T>>>((const float2*)feat, (float2*)out_r);
        } else {
            if (rb) k_prop<0, 1><<<gW, T>>>((const float2*)feat, (float2*)out_r);
            else    k_prop<0, 0><<<gW, T>>>((const float2*)feat, (float2*)out_r);
        }
    }

    // ---- FFN + residual ----
    const int TF = 128;
    k_ffn<<<(NN + TF - 1) / TF, TF>>>(out_r, feat, w1, b1, w2, b2, out_rst);
}